// round 5
// baseline (speedup 1.0000x reference)
#include <cuda_runtime.h>
#include <cstdint>

#define Bsz 4
#define Sl 4096
#define Dm 1024
#define Hh 16
#define HD 64
#define SPLIT 16
#define BH (Bsz * Hh)

// GEMM-D tiling (mma.sync tf32)
#define TM 256
#define TN 128
#define BK 32
#define NS 3
#define NCHUNK (Dm / BK)
#define KPAD 36                      // row stride in floats (144B)
#define A_FLOATS (TM * KPAD)
#define B_FLOATS (TN * KPAD)
#define STAGE_FLOATS (A_FLOATS + B_FLOATS)
#define SMEM_DYN (NS * STAGE_FLOATS * 4)

// Scratch (allocation-free rule: device globals)
__device__ float g_KV_part[SPLIT * BH * HD * HD];
__device__ float g_KV[BH * HD * HD];
__device__ float g_W2[Bsz * Dm * Dm];   // holds tf32-bit-pattern floats

// ---------------------------------------------------------------------------
// helpers
// ---------------------------------------------------------------------------
__device__ __forceinline__ uint32_t smem_u32(const void* p) {
    uint32_t a;
    asm("{ .reg .u64 t; cvta.to.shared.u64 t, %1; cvt.u32.u64 %0, t; }"
        : "=r"(a) : "l"(p));
    return a;
}
__device__ __forceinline__ void cp4(uint32_t dst, const void* src) {
    asm volatile("cp.async.ca.shared.global [%0], [%1], 4;" :: "r"(dst), "l"(src));
}
__device__ __forceinline__ uint32_t f2tf32(float f) {
    uint32_t r;
    asm("cvt.rna.tf32.f32 %0, %1;" : "=r"(r) : "f"(f));
    return r;
}
__device__ __forceinline__ void mma_tf32_16n8k8(float* c, uint32_t a0, uint32_t a1,
                                                uint32_t a2, uint32_t a3,
                                                uint32_t b0, uint32_t b1) {
    asm volatile(
        "mma.sync.aligned.m16n8k8.row.col.f32.tf32.tf32.f32 "
        "{%0,%1,%2,%3}, {%4,%5,%6,%7}, {%8,%9}, {%0,%1,%2,%3};"
        : "+f"(c[0]), "+f"(c[1]), "+f"(c[2]), "+f"(c[3])
        : "r"(a0), "r"(a1), "r"(a2), "r"(a3), "r"(b0), "r"(b1));
}
// permuted k position within a 32-wide row
#define PERM(k) (((k) & 3) * 8 + ((k) >> 2))

// ---------------------------------------------------------------------------
// Kernel A: partial KV[b,h,d,e] = sum_{s in split} K[b,s,h*64+d]*V[b,s,h*64+e]
// ---------------------------------------------------------------------------
__global__ __launch_bounds__(256) void kv_partial_kernel(
    const float* __restrict__ K, const float* __restrict__ V)
{
    int bh = blockIdx.x;
    int sp = blockIdx.y;
    int b = bh >> 4, h = bh & 15;
    int t = threadIdx.x;

    __shared__ float Ks[32][64];
    __shared__ float Vs[32][64];

    float acc[4][4] = {};
    int d0 = (t & 15) * 4;
    int e0 = (t >> 4) * 4;

    const float* Kbase = K + ((size_t)b * Sl) * Dm + h * HD;
    const float* Vbase = V + ((size_t)b * Sl) * Dm + h * HD;
    int s_begin = sp * (Sl / SPLIT);

    for (int sc = 0; sc < (Sl / SPLIT); sc += 32) {
#pragma unroll
        for (int r = 0; r < 2; r++) {
            int idx = t + r * 256;
            int row = idx >> 4;
            int c4 = (idx & 15) * 4;
            size_t goff = (size_t)(s_begin + sc + row) * Dm + c4;
            float4 kv4 = *(const float4*)(Kbase + goff);
            float4 vv4 = *(const float4*)(Vbase + goff);
            *(float4*)&Ks[row][c4] = kv4;
            *(float4*)&Vs[row][c4] = vv4;
        }
        __syncthreads();
#pragma unroll
        for (int ss = 0; ss < 32; ss++) {
            float4 kd = *(const float4*)&Ks[ss][d0];
            float4 ve = *(const float4*)&Vs[ss][e0];
            float kk[4] = {kd.x, kd.y, kd.z, kd.w};
            float vv[4] = {ve.x, ve.y, ve.z, ve.w};
#pragma unroll
            for (int i = 0; i < 4; i++)
#pragma unroll
                for (int j = 0; j < 4; j++)
                    acc[i][j] += kk[i] * vv[j];
        }
        __syncthreads();
    }

    float* out = g_KV_part + ((size_t)sp * BH + bh) * (HD * HD);
#pragma unroll
    for (int i = 0; i < 4; i++)
#pragma unroll
        for (int j = 0; j < 4; j++)
            out[(d0 + i) * HD + (e0 + j)] = acc[i][j];
}

// ---------------------------------------------------------------------------
// Kernel B: deterministic reduction of SPLIT partials
// ---------------------------------------------------------------------------
__global__ __launch_bounds__(256) void kv_reduce_kernel()
{
    int idx = blockIdx.x * 256 + threadIdx.x;
    float s = 0.f;
#pragma unroll
    for (int p = 0; p < SPLIT; p++)
        s += g_KV_part[(size_t)p * (BH * HD * HD) + idx];
    g_KV[idx] = s;
}

// ---------------------------------------------------------------------------
// Kernel C: W2[b][o][h*64+d] = sum_e KV[b,h,d,e] * W[o*Dm + h*64 + e]
// Stores tf32-converted bit patterns (consumed raw by kernel D's B operand).
// ---------------------------------------------------------------------------
__global__ __launch_bounds__(256) void w2_kernel(const float* __restrict__ W)
{
    int bh = blockIdx.x;
    int ot = blockIdx.y;
    int b = bh >> 4, h = bh & 15;
    int t = threadIdx.x;
    int o_base = ot * 64;

    __shared__ float KVt[64][68];
    __shared__ float WsT[64][68];

    for (int idx = t; idx < 4096; idx += 256) {
        int r = idx >> 6;
        int c = idx & 63;
        KVt[c][r] = g_KV[(size_t)bh * 4096 + idx];
        WsT[c][r] = W[(size_t)(o_base + r) * Dm + h * HD + c];
    }
    __syncthreads();

    int d0 = (t & 15) * 4;
    int o0 = (t >> 4) * 4;
    float acc[4][4] = {};
#pragma unroll 8
    for (int e = 0; e < 64; e++) {
        float4 wv = *(const float4*)&WsT[e][o0];
        float4 kv = *(const float4*)&KVt[e][d0];
        float ww[4] = {wv.x, wv.y, wv.z, wv.w};
        float kk[4] = {kv.x, kv.y, kv.z, kv.w};
#pragma unroll
        for (int i = 0; i < 4; i++)
#pragma unroll
            for (int j = 0; j < 4; j++)
                acc[i][j] += ww[i] * kk[j];
    }
#pragma unroll
    for (int i = 0; i < 4; i++)
#pragma unroll
        for (int j = 0; j < 4; j++)
            g_W2[((size_t)b * Dm + (o_base + o0 + i)) * Dm + h * HD + d0 + j] =
                __uint_as_float(f2tf32(acc[i][j]));
}

// ---------------------------------------------------------------------------
// Kernel D: out[b,m,n] = sum_k Q[b,m,k]*W2[b,n,k] + bias[n]
// mma.sync tf32 m16n8k8. CTA 256x128, BK=32, 512 thr (16 warps 4x4),
// warp tile 64x32. 3-stage cp.async pipeline with permuted-k smem layout:
// element k stored at PERM(k) so one LDS.128 = fragments for 2 k-steps.
// ---------------------------------------------------------------------------
__global__ __launch_bounds__(512, 1) void out_gemm_tc(
    const float* __restrict__ Q, const float* __restrict__ bias,
    float* __restrict__ Out)
{
    extern __shared__ float smem[];

    const int t   = threadIdx.x;
    const int wid = t >> 5;
    const int lid = t & 31;
    const int g   = lid >> 2;       // 0..7
    const int tig = lid & 3;        // 0..3
    const int wm  = wid >> 2;       // 0..3 (M)
    const int wn  = wid & 3;        // 0..3 (N)

    const int m0 = blockIdx.x * TM;
    const int n0 = blockIdx.y * TN;
    const int b  = blockIdx.z;

    const float* Ag = Q    + (size_t)b * Sl * Dm + (size_t)m0 * Dm;
    const float* Bg = g_W2 + (size_t)b * Dm * Dm + (size_t)n0 * Dm;

    const uint32_t u0 = smem_u32(smem);

    // stage load: A 256x32, B 128x32; one warp per row, 4B cp.async,
    // permuted destination (PERM(lane) is a permutation -> conflict-free).
    auto load_stage = [&](int s, int k0) {
        uint32_t uA = u0 + (s * STAGE_FLOATS) * 4;
        uint32_t uB = uA + A_FLOATS * 4;
        int row0 = t >> 5;
        int k    = t & 31;
        uint32_t p4 = PERM(k) * 4;
#pragma unroll
        for (int i = 0; i < 16; i++) {          // A: 256 rows, 16 warps
            int row = row0 + i * 16;
            cp4(uA + row * (KPAD * 4) + p4, Ag + (size_t)row * Dm + k0 + k);
        }
#pragma unroll
        for (int i = 0; i < 8; i++) {           // B: 128 rows
            int row = row0 + i * 16;
            cp4(uB + row * (KPAD * 4) + p4, Bg + (size_t)row * Dm + k0 + k);
        }
    };

    float acc[4][4][4] = {};

    load_stage(0, 0);
    asm volatile("cp.async.commit_group;" ::: "memory");
    load_stage(1, BK);
    asm volatile("cp.async.commit_group;" ::: "memory");
    load_stage(2, 2 * BK);
    asm volatile("cp.async.commit_group;" ::: "memory");

    // per-thread fragment base offsets (in floats)
    const int aoff = (wm * 64 + g) * KPAD + tig * 8;
    const int boff = (wn * 32 + g) * KPAD + tig * 8;

    int s = 0;
    for (int i = 0; i < NCHUNK; i++) {
        asm volatile("cp.async.wait_group %0;" :: "n"(NS - 1) : "memory");
        __syncthreads();

        const float* As = smem + s * STAGE_FLOATS;
        const float* Bs = As + A_FLOATS;

#pragma unroll
        for (int hs = 0; hs < 2; hs++) {        // half-chunk: k-steps 2hs, 2hs+1
            // A fragments: lo = row+g, hi = row+g+8; cvt to tf32 (RNA)
            uint32_t alo[4][4], ahi[4][4];
#pragma unroll
            for (int mi = 0; mi < 4; mi++) {
                float4 lo = *(const float4*)&As[aoff + mi * 16 * KPAD + hs * 4];
                float4 hi = *(const float4*)&As[aoff + (mi * 16 + 8) * KPAD + hs * 4];
                alo[mi][0] = f2tf32(lo.x); alo[mi][1] = f2tf32(lo.y);
                alo[mi][2] = f2tf32(lo.z); alo[mi][3] = f2tf32(lo.w);
                ahi[mi][0] = f2tf32(hi.x); ahi[mi][1] = f2tf32(hi.y);
                ahi[mi][2] = f2tf32(hi.z); ahi[mi][3] = f2tf32(hi.w);
            }
            // B fragments: already tf32 bits, use raw
            uint4 bf[4];
#pragma unroll
            for (int ni = 0; ni < 4; ni++)
                bf[ni] = *(const uint4*)&Bs[boff + ni * 8 * KPAD + hs * 4];

#pragma unroll
            for (int mi = 0; mi < 4; mi++)
#pragma unroll
                for (int ni = 0; ni < 4; ni++) {
                    // k-step 2hs
                    mma_tf32_16n8k8(acc[mi][ni],
                                    alo[mi][0], ahi[mi][0], alo[mi][1], ahi[mi][1],
                                    bf[ni].x, bf[ni].y);
                    // k-step 2hs+1
                    mma_tf32_16n8k8(acc[mi][ni],
                                    alo[mi][2], ahi[mi][2], alo[mi][3], ahi[mi][3],
                                    bf[ni].z, bf[ni].w);
                }
        }

        __syncthreads();
        if (i + NS < NCHUNK)
            load_stage(s, (i + NS) * BK);
        asm volatile("cp.async.commit_group;" ::: "memory");
        if (++s == NS) s = 0;
    }

    // epilogue: add bias, store
    float* C = Out + (size_t)b * Sl * Dm;
#pragma unroll
    for (int mi = 0; mi < 4; mi++) {
        int row = m0 + wm * 64 + mi * 16 + g;
#pragma unroll
        for (int ni = 0; ni < 4; ni++) {
            int col = n0 + wn * 32 + ni * 8 + tig * 2;
            float bx = bias[col], by = bias[col + 1];
            float2 r0 = { acc[mi][ni][0] + bx, acc[mi][ni][1] + by };
            float2 r1 = { acc[mi][ni][2] + bx, acc[mi][ni][3] + by };
            *(float2*)(C + (size_t)row * Dm + col)       = r0;
            *(float2*)(C + (size_t)(row + 8) * Dm + col) = r1;
        }
    }
}

// ---------------------------------------------------------------------------
extern "C" void kernel_launch(void* const* d_in, const int* in_sizes, int n_in,
                              void* d_out, int out_size)
{
    const float* Q    = (const float*)d_in[0];
    const float* K    = (const float*)d_in[1];
    const float* V    = (const float*)d_in[2];
    const float* Wout = (const float*)d_in[3];
    const float* bout = (const float*)d_in[4];
    float* Out = (float*)d_out;

    static bool attr_done = false;
    if (!attr_done) {
        cudaFuncSetAttribute(out_gemm_tc,
                             cudaFuncAttributeMaxDynamicSharedMemorySize, SMEM_DYN);
        attr_done = true;
    }

    kv_partial_kernel<<<dim3(BH, SPLIT), 256>>>(K, V);
    kv_reduce_kernel<<<dim3(BH * HD * HD / 256), 256>>>();
    w2_kernel<<<dim3(BH, Dm / 64), 256>>>(Wout);
    out_gemm_tc<<<dim3(Sl / TM, Dm / TN, Bsz), 512, SMEM_DYN>>>(Q, bout, Out);
}

// round 6
// speedup vs baseline: 1.3562x; 1.3562x over previous
#include <cuda_runtime.h>
#include <cstdint>

#define Bsz 4
#define Sl 4096
#define Dm 1024
#define Hh 16
#define HD 64
#define SPLIT 16
#define BH (Bsz * Hh)

// GEMM-D tiling (mma.sync tf32 + ldmatrix)
#define TM 128
#define TN 128
#define BK 32
#define NS 3
#define NCHUNK (Dm / BK)
#define KPAD 36                      // row stride in floats (144B = 9*16B)
#define A_FLOATS (TM * KPAD)
#define B_FLOATS (TN * KPAD)
#define STAGE_FLOATS (A_FLOATS + B_FLOATS)
#define SMEM_DYN (NS * STAGE_FLOATS * 4)   // 110592 B

// Scratch (allocation-free rule: device globals)
__device__ float g_KV_part[SPLIT * BH * HD * HD];
__device__ float g_KV[BH * HD * HD];
__device__ float g_W2[Bsz * Dm * Dm];    // tf32-bit-pattern floats
__device__ float g_Qtf[Bsz * Sl * Dm];   // tf32-bit-pattern Q

// ---------------------------------------------------------------------------
// helpers
// ---------------------------------------------------------------------------
__device__ __forceinline__ uint32_t smem_u32(const void* p) {
    uint32_t a;
    asm("{ .reg .u64 t; cvta.to.shared.u64 t, %1; cvt.u32.u64 %0, t; }"
        : "=r"(a) : "l"(p));
    return a;
}
__device__ __forceinline__ void cp16(uint32_t dst, const void* src) {
    asm volatile("cp.async.cg.shared.global [%0], [%1], 16;" :: "r"(dst), "l"(src));
}
__device__ __forceinline__ uint32_t f2tf32(float f) {
    uint32_t r;
    asm("cvt.rna.tf32.f32 %0, %1;" : "=r"(r) : "f"(f));
    return r;
}
__device__ __forceinline__ void ldsm4(uint32_t* d, uint32_t addr) {
    asm volatile("ldmatrix.sync.aligned.m8n8.x4.shared.b16 {%0,%1,%2,%3}, [%4];"
        : "=r"(d[0]), "=r"(d[1]), "=r"(d[2]), "=r"(d[3]) : "r"(addr));
}
__device__ __forceinline__ void mma_tf32_16n8k8(float* c, uint32_t a0, uint32_t a1,
                                                uint32_t a2, uint32_t a3,
                                                uint32_t b0, uint32_t b1) {
    asm volatile(
        "mma.sync.aligned.m16n8k8.row.col.f32.tf32.tf32.f32 "
        "{%0,%1,%2,%3}, {%4,%5,%6,%7}, {%8,%9}, {%0,%1,%2,%3};"
        : "+f"(c[0]), "+f"(c[1]), "+f"(c[2]), "+f"(c[3])
        : "r"(a0), "r"(a1), "r"(a2), "r"(a3), "r"(b0), "r"(b1));
}

// ---------------------------------------------------------------------------
// Kernel Qc: Q -> tf32 bit patterns (RNA), once
// ---------------------------------------------------------------------------
__global__ __launch_bounds__(256) void qconv_kernel(const float* __restrict__ Q)
{
    size_t i = ((size_t)blockIdx.x * 256 + threadIdx.x) * 4;
    float4 v = *(const float4*)(Q + i);
    float4 o;
    o.x = __uint_as_float(f2tf32(v.x));
    o.y = __uint_as_float(f2tf32(v.y));
    o.z = __uint_as_float(f2tf32(v.z));
    o.w = __uint_as_float(f2tf32(v.w));
    *(float4*)(g_Qtf + i) = o;
}

// ---------------------------------------------------------------------------
// Kernel A: partial KV[b,h,d,e] = sum_{s in split} K[b,s,h*64+d]*V[b,s,h*64+e]
// ---------------------------------------------------------------------------
__global__ __launch_bounds__(256) void kv_partial_kernel(
    const float* __restrict__ K, const float* __restrict__ V)
{
    int bh = blockIdx.x;
    int sp = blockIdx.y;
    int b = bh >> 4, h = bh & 15;
    int t = threadIdx.x;

    __shared__ float Ks[32][64];
    __shared__ float Vs[32][64];

    float acc[4][4] = {};
    int d0 = (t & 15) * 4;
    int e0 = (t >> 4) * 4;

    const float* Kbase = K + ((size_t)b * Sl) * Dm + h * HD;
    const float* Vbase = V + ((size_t)b * Sl) * Dm + h * HD;
    int s_begin = sp * (Sl / SPLIT);

    for (int sc = 0; sc < (Sl / SPLIT); sc += 32) {
#pragma unroll
        for (int r = 0; r < 2; r++) {
            int idx = t + r * 256;
            int row = idx >> 4;
            int c4 = (idx & 15) * 4;
            size_t goff = (size_t)(s_begin + sc + row) * Dm + c4;
            float4 kv4 = *(const float4*)(Kbase + goff);
            float4 vv4 = *(const float4*)(Vbase + goff);
            *(float4*)&Ks[row][c4] = kv4;
            *(float4*)&Vs[row][c4] = vv4;
        }
        __syncthreads();
#pragma unroll
        for (int ss = 0; ss < 32; ss++) {
            float4 kd = *(const float4*)&Ks[ss][d0];
            float4 ve = *(const float4*)&Vs[ss][e0];
            float kk[4] = {kd.x, kd.y, kd.z, kd.w};
            float vv[4] = {ve.x, ve.y, ve.z, ve.w};
#pragma unroll
            for (int i = 0; i < 4; i++)
#pragma unroll
                for (int j = 0; j < 4; j++)
                    acc[i][j] += kk[i] * vv[j];
        }
        __syncthreads();
    }

    float* out = g_KV_part + ((size_t)sp * BH + bh) * (HD * HD);
#pragma unroll
    for (int i = 0; i < 4; i++)
#pragma unroll
        for (int j = 0; j < 4; j++)
            out[(d0 + i) * HD + (e0 + j)] = acc[i][j];
}

// ---------------------------------------------------------------------------
// Kernel B: deterministic reduction of SPLIT partials
// ---------------------------------------------------------------------------
__global__ __launch_bounds__(256) void kv_reduce_kernel()
{
    int idx = blockIdx.x * 256 + threadIdx.x;
    float s = 0.f;
#pragma unroll
    for (int p = 0; p < SPLIT; p++)
        s += g_KV_part[(size_t)p * (BH * HD * HD) + idx];
    g_KV[idx] = s;
}

// ---------------------------------------------------------------------------
// Kernel C: W2[b][o][h*64+d] = sum_e KV[b,h,d,e] * W[o*Dm + h*64 + e]
// Stores tf32 bit patterns (kernel D's B operand).
// ---------------------------------------------------------------------------
__global__ __launch_bounds__(256) void w2_kernel(const float* __restrict__ W)
{
    int bh = blockIdx.x;
    int ot = blockIdx.y;
    int b = bh >> 4, h = bh & 15;
    int t = threadIdx.x;
    int o_base = ot * 64;

    __shared__ float KVt[64][68];
    __shared__ float WsT[64][68];

    for (int idx = t; idx < 4096; idx += 256) {
        int r = idx >> 6;
        int c = idx & 63;
        KVt[c][r] = g_KV[(size_t)bh * 4096 + idx];
        WsT[c][r] = W[(size_t)(o_base + r) * Dm + h * HD + c];
    }
    __syncthreads();

    int d0 = (t & 15) * 4;
    int o0 = (t >> 4) * 4;
    float acc[4][4] = {};
#pragma unroll 8
    for (int e = 0; e < 64; e++) {
        float4 wv = *(const float4*)&WsT[e][o0];
        float4 kv = *(const float4*)&KVt[e][d0];
        float ww[4] = {wv.x, wv.y, wv.z, wv.w};
        float kk[4] = {kv.x, kv.y, kv.z, kv.w};
#pragma unroll
        for (int i = 0; i < 4; i++)
#pragma unroll
            for (int j = 0; j < 4; j++)
                acc[i][j] += ww[i] * kk[j];
    }
#pragma unroll
    for (int i = 0; i < 4; i++)
#pragma unroll
        for (int j = 0; j < 4; j++)
            g_W2[((size_t)b * Dm + (o_base + o0 + i)) * Dm + h * HD + d0 + j] =
                __uint_as_float(f2tf32(acc[i][j]));
}

// ---------------------------------------------------------------------------
// Kernel D: out[b,m,n] = sum_k Qtf[b,m,k]*W2[b,n,k] + bias[n]
// mma.sync tf32 m16n8k8 + ldmatrix.x4 fragments, no in-loop cvt.
// CTA 128x128, 256 thr (8 warps, 2x4), warp tile 64x32, BK=32, NS=3,
// single __syncthreads per chunk, 2 CTAs/SM.
// ---------------------------------------------------------------------------
__global__ __launch_bounds__(256, 2) void out_gemm_tc(
    const float* __restrict__ bias, float* __restrict__ Out)
{
    extern __shared__ float smem[];

    const int t   = threadIdx.x;
    const int wid = t >> 5;
    const int lid = t & 31;
    const int g   = lid >> 2;
    const int tig = lid & 3;
    const int wm  = wid >> 2;       // 0..1 (M)
    const int wn  = wid & 3;        // 0..3 (N)

    const int m0 = blockIdx.x * TM;
    const int n0 = blockIdx.y * TN;
    const int b  = blockIdx.z;

    const float* Ag = g_Qtf + (size_t)b * Sl * Dm + (size_t)m0 * Dm;
    const float* Bg = g_W2  + (size_t)b * Dm * Dm + (size_t)n0 * Dm;

    const uint32_t u0 = smem_u32(smem);

    // stage load: A 128 rows x 32 floats, B 128 rows x 32 floats, 16B cp.async
    auto load_stage = [&](int s, int k0) {
        uint32_t uA = u0 + (uint32_t)(s * STAGE_FLOATS) * 4;
        uint32_t uB = uA + A_FLOATS * 4;
#pragma unroll
        for (int i = 0; i < 4; i++) {
            int idx = t + (i << 8);
            int row = idx >> 3, c = idx & 7;
            cp16(uA + row * (KPAD * 4) + c * 16, Ag + (size_t)row * Dm + k0 + c * 4);
        }
#pragma unroll
        for (int i = 0; i < 4; i++) {
            int idx = t + (i << 8);
            int row = idx >> 3, c = idx & 7;
            cp16(uB + row * (KPAD * 4) + c * 16, Bg + (size_t)row * Dm + k0 + c * 4);
        }
    };

    float acc[4][4][4] = {};

    load_stage(0, 0);
    asm volatile("cp.async.commit_group;" ::: "memory");
    load_stage(1, BK);
    asm volatile("cp.async.commit_group;" ::: "memory");

    // per-lane ldmatrix base offsets (bytes)
    // A: matrices (m0-7,k0-3),(m8-15,k0-3),(m0-7,k4-7),(m8-15,k4-7)
    const uint32_t aBase = (uint32_t)(wm * 64 + (lid & 15)) * (KPAD * 4)
                         + (uint32_t)(lid >> 4) * 16;
    // B: matrices (n0-7,k0-3),(n0-7,k4-7),(n8-15,k0-3),(n8-15,k4-7)
    const uint32_t bBase = (uint32_t)(wn * 32 + ((lid >> 4) << 3) + (lid & 7)) * (KPAD * 4)
                         + (uint32_t)((lid >> 3) & 1) * 16;

    int s = 0;
    for (int i = 0; i < NCHUNK; i++) {
        asm volatile("cp.async.wait_group 1;" ::: "memory");
        __syncthreads();

        if (i + 2 < NCHUNK) {
            int sn = s + 2; if (sn >= NS) sn -= NS;
            load_stage(sn, (i + 2) * BK);
        }
        asm volatile("cp.async.commit_group;" ::: "memory");

        uint32_t uA = u0 + (uint32_t)(s * STAGE_FLOATS) * 4;
        uint32_t uB = uA + A_FLOATS * 4;

#pragma unroll
        for (int ks = 0; ks < 4; ks++) {
            uint32_t af[4][4];
#pragma unroll
            for (int mi = 0; mi < 4; mi++)
                ldsm4(af[mi], uA + aBase + mi * 16 * (KPAD * 4) + ks * 32);
            uint32_t bf[2][4];
#pragma unroll
            for (int p = 0; p < 2; p++)
                ldsm4(bf[p], uB + bBase + p * 16 * (KPAD * 4) + ks * 32);
#pragma unroll
            for (int mi = 0; mi < 4; mi++)
#pragma unroll
                for (int ni = 0; ni < 4; ni++) {
                    const int p = ni >> 1, q = (ni & 1) * 2;
                    mma_tf32_16n8k8(acc[mi][ni],
                                    af[mi][0], af[mi][1], af[mi][2], af[mi][3],
                                    bf[p][q], bf[p][q + 1]);
                }
        }
        if (++s == NS) s = 0;
    }

    // epilogue: add bias, store
    float* C = Out + (size_t)b * Sl * Dm;
#pragma unroll
    for (int mi = 0; mi < 4; mi++) {
        int row = m0 + wm * 64 + mi * 16 + g;
#pragma unroll
        for (int ni = 0; ni < 4; ni++) {
            int col = n0 + wn * 32 + ni * 8 + tig * 2;
            float bx = bias[col], by = bias[col + 1];
            float2 r0 = { acc[mi][ni][0] + bx, acc[mi][ni][1] + by };
            float2 r1 = { acc[mi][ni][2] + bx, acc[mi][ni][3] + by };
            *(float2*)(C + (size_t)row * Dm + col)       = r0;
            *(float2*)(C + (size_t)(row + 8) * Dm + col) = r1;
        }
    }
}

// ---------------------------------------------------------------------------
extern "C" void kernel_launch(void* const* d_in, const int* in_sizes, int n_in,
                              void* d_out, int out_size)
{
    const float* Q    = (const float*)d_in[0];
    const float* K    = (const float*)d_in[1];
    const float* V    = (const float*)d_in[2];
    const float* Wout = (const float*)d_in[3];
    const float* bout = (const float*)d_in[4];
    float* Out = (float*)d_out;

    static bool attr_done = false;
    if (!attr_done) {
        cudaFuncSetAttribute(out_gemm_tc,
                             cudaFuncAttributeMaxDynamicSharedMemorySize, SMEM_DYN);
        attr_done = true;
    }

    qconv_kernel<<<dim3(Bsz * Sl * Dm / 1024), 256>>>(Q);
    kv_partial_kernel<<<dim3(BH, SPLIT), 256>>>(K, V);
    kv_reduce_kernel<<<dim3(BH * HD * HD / 256), 256>>>();
    w2_kernel<<<dim3(BH, Dm / 64), 256>>>(Wout);
    out_gemm_tc<<<dim3(Sl / TM, Dm / TN, Bsz), 256, SMEM_DYN>>>(bout, Out);
}

// round 7
// speedup vs baseline: 1.4251x; 1.0508x over previous
#include <cuda_runtime.h>
#include <cstdint>

#define Bsz 4
#define Sl 4096
#define Dm 1024
#define Hh 16
#define HD 64
#define SPLIT 16
#define BH (Bsz * Hh)

// GEMM-D tiling (mma.sync tf32 + ldmatrix)
#define TM 128
#define TN 128
#define BK 32
#define NS 3
#define NCHUNK (Dm / BK)
#define KPAD 36                      // row stride in floats (144B = 9*16B)
#define A_FLOATS (TM * KPAD)
#define B_FLOATS (TN * KPAD)
#define STAGE_FLOATS (A_FLOATS + B_FLOATS)
#define SMEM_DYN (NS * STAGE_FLOATS * 4)   // 110592 B

// Scratch (allocation-free rule: device globals)
__device__ float g_KV_part[SPLIT * BH * HD * HD];
__device__ float g_KV[BH * HD * HD];
__device__ float g_W2[Bsz * Dm * Dm];    // tf32-bit-pattern floats
__device__ float g_Qtf[Bsz * Sl * Dm];   // tf32-bit-pattern Q

// ---------------------------------------------------------------------------
// helpers
// ---------------------------------------------------------------------------
__device__ __forceinline__ uint32_t smem_u32(const void* p) {
    uint32_t a;
    asm("{ .reg .u64 t; cvta.to.shared.u64 t, %1; cvt.u32.u64 %0, t; }"
        : "=r"(a) : "l"(p));
    return a;
}
__device__ __forceinline__ void cp16(uint32_t dst, const void* src) {
    asm volatile("cp.async.cg.shared.global [%0], [%1], 16;" :: "r"(dst), "l"(src));
}
__device__ __forceinline__ uint32_t f2tf32(float f) {
    uint32_t r;
    asm("cvt.rna.tf32.f32 %0, %1;" : "=r"(r) : "f"(f));
    return r;
}
__device__ __forceinline__ void ldsm4(uint32_t* d, uint32_t addr) {
    asm volatile("ldmatrix.sync.aligned.m8n8.x4.shared.b16 {%0,%1,%2,%3}, [%4];"
        : "=r"(d[0]), "=r"(d[1]), "=r"(d[2]), "=r"(d[3]) : "r"(addr));
}
__device__ __forceinline__ void mma_tf32_16n8k8(float* c, uint32_t a0, uint32_t a1,
                                                uint32_t a2, uint32_t a3,
                                                uint32_t b0, uint32_t b1) {
    asm volatile(
        "mma.sync.aligned.m16n8k8.row.col.f32.tf32.tf32.f32 "
        "{%0,%1,%2,%3}, {%4,%5,%6,%7}, {%8,%9}, {%0,%1,%2,%3};"
        : "+f"(c[0]), "+f"(c[1]), "+f"(c[2]), "+f"(c[3])
        : "r"(a0), "r"(a1), "r"(a2), "r"(a3), "r"(b0), "r"(b1));
}

// ---------------------------------------------------------------------------
// Kernel AQ (fused): blocks [0,1024): partial KV; blocks [1024,1536): Q->tf32.
// The KV part is FFMA-bound, the Q part is pure HBM; they overlap.
// ---------------------------------------------------------------------------
__global__ __launch_bounds__(256) void kv_q_kernel(
    const float* __restrict__ K, const float* __restrict__ V,
    const float* __restrict__ Q)
{
    const int blk = blockIdx.x;
    const int t = threadIdx.x;

    if (blk >= BH * SPLIT) {
        // ---- Q -> tf32 bit patterns (RNA), 32 float4 per thread ----
        size_t f4 = (size_t)(blk - BH * SPLIT) * 8192 + t;
#pragma unroll 4
        for (int j = 0; j < 32; j++) {
            size_t i = (f4 + (size_t)j * 256) * 4;
            float4 v = *(const float4*)(Q + i);
            float4 o;
            o.x = __uint_as_float(f2tf32(v.x));
            o.y = __uint_as_float(f2tf32(v.y));
            o.z = __uint_as_float(f2tf32(v.z));
            o.w = __uint_as_float(f2tf32(v.w));
            *(float4*)(g_Qtf + i) = o;
        }
        return;
    }

    // ---- partial KV[b,h,d,e] over one S-split ----
    int bh = blk & (BH - 1);
    int sp = blk >> 6;
    int b = bh >> 4, h = bh & 15;

    __shared__ float Ks[32][64];
    __shared__ float Vs[32][64];

    float acc[4][4] = {};
    int d0 = (t & 15) * 4;
    int e0 = (t >> 4) * 4;

    const float* Kbase = K + ((size_t)b * Sl) * Dm + h * HD;
    const float* Vbase = V + ((size_t)b * Sl) * Dm + h * HD;
    int s_begin = sp * (Sl / SPLIT);

    for (int sc = 0; sc < (Sl / SPLIT); sc += 32) {
#pragma unroll
        for (int r = 0; r < 2; r++) {
            int idx = t + r * 256;
            int row = idx >> 4;
            int c4 = (idx & 15) * 4;
            size_t goff = (size_t)(s_begin + sc + row) * Dm + c4;
            float4 kv4 = *(const float4*)(Kbase + goff);
            float4 vv4 = *(const float4*)(Vbase + goff);
            *(float4*)&Ks[row][c4] = kv4;
            *(float4*)&Vs[row][c4] = vv4;
        }
        __syncthreads();
#pragma unroll
        for (int ss = 0; ss < 32; ss++) {
            float4 kd = *(const float4*)&Ks[ss][d0];
            float4 ve = *(const float4*)&Vs[ss][e0];
            float kk[4] = {kd.x, kd.y, kd.z, kd.w};
            float vv[4] = {ve.x, ve.y, ve.z, ve.w};
#pragma unroll
            for (int i = 0; i < 4; i++)
#pragma unroll
                for (int j = 0; j < 4; j++)
                    acc[i][j] += kk[i] * vv[j];
        }
        __syncthreads();
    }

    float* out = g_KV_part + ((size_t)sp * BH + bh) * (HD * HD);
#pragma unroll
    for (int i = 0; i < 4; i++)
#pragma unroll
        for (int j = 0; j < 4; j++)
            out[(d0 + i) * HD + (e0 + j)] = acc[i][j];
}

// ---------------------------------------------------------------------------
// Kernel B: deterministic reduction of SPLIT partials
// ---------------------------------------------------------------------------
__global__ __launch_bounds__(256) void kv_reduce_kernel()
{
    int idx = blockIdx.x * 256 + threadIdx.x;
    float s = 0.f;
#pragma unroll
    for (int p = 0; p < SPLIT; p++)
        s += g_KV_part[(size_t)p * (BH * HD * HD) + idx];
    g_KV[idx] = s;
}

// ---------------------------------------------------------------------------
// Kernel C: W2[b][o][h*64+d] = sum_e KV[b,h,d,e] * W[o*Dm + h*64 + e]
// 128 threads, tile o=128 x d=64, 8x8 per thread (64 FMA / 16 smem floats).
// Transpose fills are STS-conflict-free (warp = 32 consecutive rows, fixed col).
// Stores tf32 bit patterns. grid (BH, Dm/128).
// ---------------------------------------------------------------------------
__global__ __launch_bounds__(128) void w2_kernel(const float* __restrict__ W)
{
    __shared__ float KVt[64][64];    // [e][d]
    __shared__ float WsT[64][128];   // [e][o]

    const int bh = blockIdx.x;
    const int b = bh >> 4, h = bh & 15;
    const int t = threadIdx.x;
    const int o_base = blockIdx.y * 128;

    // fill KVt: KV[d][e] -> KVt[e][d]; warp covers 32 consecutive d at fixed e4
#pragma unroll
    for (int i = 0; i < 8; i++) {
        int idx = t + i * 128;              // 1024 float4 chunks
        int rd = idx & 63;                  // d row
        int c4 = (idx >> 6) * 4;            // e chunk
        float4 v = *(const float4*)(g_KV + (size_t)bh * 4096 + rd * 64 + c4);
        KVt[c4 + 0][rd] = v.x; KVt[c4 + 1][rd] = v.y;
        KVt[c4 + 2][rd] = v.z; KVt[c4 + 3][rd] = v.w;
    }
    // fill WsT: W[o][e] -> WsT[e][o]; warp covers 32 consecutive o at fixed e4
#pragma unroll
    for (int i = 0; i < 16; i++) {
        int idx = t + i * 128;              // 2048 float4 chunks
        int ro = idx & 127;                 // o row
        int c4 = (idx >> 7) * 4;            // e chunk
        float4 v = *(const float4*)(W + (size_t)(o_base + ro) * Dm + h * HD + c4);
        WsT[c4 + 0][ro] = v.x; WsT[c4 + 1][ro] = v.y;
        WsT[c4 + 2][ro] = v.z; WsT[c4 + 3][ro] = v.w;
    }
    __syncthreads();

    const int d0 = (t & 7) * 8;
    const int o0 = (t >> 3) * 8;
    float acc[8][8] = {};
#pragma unroll 4
    for (int e = 0; e < 64; e++) {
        float ww[8], kk[8];
        *(float4*)&ww[0] = *(const float4*)&WsT[e][o0];
        *(float4*)&ww[4] = *(const float4*)&WsT[e][o0 + 4];
        *(float4*)&kk[0] = *(const float4*)&KVt[e][d0];
        *(float4*)&kk[4] = *(const float4*)&KVt[e][d0 + 4];
#pragma unroll
        for (int i = 0; i < 8; i++)
#pragma unroll
            for (int j = 0; j < 8; j++)
                acc[i][j] += ww[i] * kk[j];
    }

#pragma unroll
    for (int i = 0; i < 8; i++) {
        float* dst = g_W2 + ((size_t)b * Dm + (o_base + o0 + i)) * Dm + h * HD + d0;
#pragma unroll
        for (int jj = 0; jj < 2; jj++) {
            float4 o;
            o.x = __uint_as_float(f2tf32(acc[i][jj * 4 + 0]));
            o.y = __uint_as_float(f2tf32(acc[i][jj * 4 + 1]));
            o.z = __uint_as_float(f2tf32(acc[i][jj * 4 + 2]));
            o.w = __uint_as_float(f2tf32(acc[i][jj * 4 + 3]));
            *(float4*)(dst + jj * 4) = o;
        }
    }
}

// ---------------------------------------------------------------------------
// Kernel D: out[b,m,n] = sum_k Qtf[b,m,k]*W2[b,n,k] + bias[n]
// mma.sync tf32 m16n8k8 + ldmatrix.x4, no in-loop cvt.
// CTA 128x128, 256 thr (8 warps 2x4), warp 64x32, BK=32, NS=3, 2 CTAs/SM.
// ---------------------------------------------------------------------------
__global__ __launch_bounds__(256, 2) void out_gemm_tc(
    const float* __restrict__ bias, float* __restrict__ Out)
{
    extern __shared__ float smem[];

    const int t   = threadIdx.x;
    const int wid = t >> 5;
    const int lid = t & 31;
    const int g   = lid >> 2;
    const int tig = lid & 3;
    const int wm  = wid >> 2;
    const int wn  = wid & 3;

    const int m0 = blockIdx.x * TM;
    const int n0 = blockIdx.y * TN;
    const int b  = blockIdx.z;

    const float* Ag = g_Qtf + (size_t)b * Sl * Dm + (size_t)m0 * Dm;
    const float* Bg = g_W2  + (size_t)b * Dm * Dm + (size_t)n0 * Dm;

    const uint32_t u0 = smem_u32(smem);

    auto load_stage = [&](int s, int k0) {
        uint32_t uA = u0 + (uint32_t)(s * STAGE_FLOATS) * 4;
        uint32_t uB = uA + A_FLOATS * 4;
#pragma unroll
        for (int i = 0; i < 4; i++) {
            int idx = t + (i << 8);
            int row = idx >> 3, c = idx & 7;
            cp16(uA + row * (KPAD * 4) + c * 16, Ag + (size_t)row * Dm + k0 + c * 4);
        }
#pragma unroll
        for (int i = 0; i < 4; i++) {
            int idx = t + (i << 8);
            int row = idx >> 3, c = idx & 7;
            cp16(uB + row * (KPAD * 4) + c * 16, Bg + (size_t)row * Dm + k0 + c * 4);
        }
    };

    float acc[4][4][4] = {};

    load_stage(0, 0);
    asm volatile("cp.async.commit_group;" ::: "memory");
    load_stage(1, BK);
    asm volatile("cp.async.commit_group;" ::: "memory");

    const uint32_t aBase = (uint32_t)(wm * 64 + (lid & 15)) * (KPAD * 4)
                         + (uint32_t)(lid >> 4) * 16;
    const uint32_t bBase = (uint32_t)(wn * 32 + ((lid >> 4) << 3) + (lid & 7)) * (KPAD * 4)
                         + (uint32_t)((lid >> 3) & 1) * 16;

    int s = 0;
    for (int i = 0; i < NCHUNK; i++) {
        asm volatile("cp.async.wait_group 1;" ::: "memory");
        __syncthreads();

        if (i + 2 < NCHUNK) {
            int sn = s + 2; if (sn >= NS) sn -= NS;
            load_stage(sn, (i + 2) * BK);
        }
        asm volatile("cp.async.commit_group;" ::: "memory");

        uint32_t uA = u0 + (uint32_t)(s * STAGE_FLOATS) * 4;
        uint32_t uB = uA + A_FLOATS * 4;

#pragma unroll
        for (int ks = 0; ks < 4; ks++) {
            uint32_t af[4][4];
#pragma unroll
            for (int mi = 0; mi < 4; mi++)
                ldsm4(af[mi], uA + aBase + mi * 16 * (KPAD * 4) + ks * 32);
            uint32_t bf[2][4];
#pragma unroll
            for (int p = 0; p < 2; p++)
                ldsm4(bf[p], uB + bBase + p * 16 * (KPAD * 4) + ks * 32);
#pragma unroll
            for (int mi = 0; mi < 4; mi++)
#pragma unroll
                for (int ni = 0; ni < 4; ni++) {
                    const int p = ni >> 1, q = (ni & 1) * 2;
                    mma_tf32_16n8k8(acc[mi][ni],
                                    af[mi][0], af[mi][1], af[mi][2], af[mi][3],
                                    bf[p][q], bf[p][q + 1]);
                }
        }
        if (++s == NS) s = 0;
    }

    float* C = Out + (size_t)b * Sl * Dm;
#pragma unroll
    for (int mi = 0; mi < 4; mi++) {
        int row = m0 + wm * 64 + mi * 16 + g;
#pragma unroll
        for (int ni = 0; ni < 4; ni++) {
            int col = n0 + wn * 32 + ni * 8 + tig * 2;
            float bx = bias[col], by = bias[col + 1];
            float2 r0 = { acc[mi][ni][0] + bx, acc[mi][ni][1] + by };
            float2 r1 = { acc[mi][ni][2] + bx, acc[mi][ni][3] + by };
            *(float2*)(C + (size_t)row * Dm + col)       = r0;
            *(float2*)(C + (size_t)(row + 8) * Dm + col) = r1;
        }
    }
}

// ---------------------------------------------------------------------------
extern "C" void kernel_launch(void* const* d_in, const int* in_sizes, int n_in,
                              void* d_out, int out_size)
{
    const float* Q    = (const float*)d_in[0];
    const float* K    = (const float*)d_in[1];
    const float* V    = (const float*)d_in[2];
    const float* Wout = (const float*)d_in[3];
    const float* bout = (const float*)d_in[4];
    float* Out = (float*)d_out;

    static bool attr_done = false;
    if (!attr_done) {
        cudaFuncSetAttribute(out_gemm_tc,
                             cudaFuncAttributeMaxDynamicSharedMemorySize, SMEM_DYN);
        attr_done = true;
    }

    kv_q_kernel<<<dim3(BH * SPLIT + 512), 256>>>(K, V, Q);
    kv_reduce_kernel<<<dim3(BH * HD * HD / 256), 256>>>();
    w2_kernel<<<dim3(BH, Dm / 128), 128>>>(Wout);
    out_gemm_tc<<<dim3(Sl / TM, Dm / TN, Bsz), 256, SMEM_DYN>>>(bout, Out);
}